// round 1
// baseline (speedup 1.0000x reference)
#include <cuda_runtime.h>
#include <math.h>
#include <stdint.h>

#define BB 4
#define NN 8192
#define KK 20
#define NK (NN*KK)
#define SPLITS 4
#define CHUNK (NN/SPLITS)
#define TILE 1024

// ------------- scratch (device globals; no allocation allowed) -------------
__device__ float    g_x[BB*6*NK];                 // [b][ch][n*K+k]  (15.7 MB)
__device__ float    g_knn_d[BB*SPLITS*NN*KK];     // partial top-20 dists
__device__ int      g_knn_i[BB*SPLITS*NN*KK];     // partial top-20 idx
__device__ float    g_mu[BB*6];                   // sum of x channels
__device__ float    g_M[BB*21];                   // sum of upper-tri x x^T
__device__ float    g_A1[BB*32], g_B1[BB*32];     // GN1 per-channel affine
__device__ float    g_sum2[BB*64], g_sq2[BB*64];  // y2 sums for GN2
__device__ unsigned g_max2[BB*64*KK], g_min2[BB*64*KK];
__device__ float    g_y3[BB*512*KK];
__device__ float    g_s3[BB*8], g_q3[BB*8];
__device__ float    g_y4[BB*1024*KK];
__device__ float    g_s4[BB*8], g_q4[BB*8];

// order-preserving float <-> uint encoding for atomic max/min
__device__ __forceinline__ unsigned fenc(float f){
    unsigned u = __float_as_uint(f);
    return (u & 0x80000000u) ? ~u : (u | 0x80000000u);
}
__device__ __forceinline__ float fdec(unsigned u){
    u = (u & 0x80000000u) ? (u & 0x7FFFFFFFu) : ~u;
    return __uint_as_float(u);
}
__device__ __forceinline__ float elu1(float v){
    return v > 0.f ? v : expm1f(v);
}

// ------------------------------- init --------------------------------------
__global__ void k_init(){
    int i = blockIdx.x*blockDim.x + threadIdx.x;
    if (i < BB*64*KK){ g_max2[i] = 0u; g_min2[i] = 0xFFFFFFFFu; }
    if (i < BB*6)  g_mu[i] = 0.f;
    if (i < BB*21) g_M[i]  = 0.f;
    if (i < BB*64){ g_sum2[i] = 0.f; g_sq2[i] = 0.f; }
    if (i < BB*8){ g_s4[i] = 0.f; g_q4[i] = 0.f; }
}

// --------------------------- KNN partial scan -------------------------------
__global__ void __launch_bounds__(128) k_knn(const float* __restrict__ pts){
    int b = blockIdx.z, s = blockIdx.y;
    int n = blockIdx.x*blockDim.x + threadIdx.x;
    const float* P = pts + (size_t)b*3*NN;
    float qx = P[n], qy = P[NN+n], qz = P[2*NN+n];
    float qs = fmaf(qz,qz, fmaf(qy,qy, qx*qx));

    __shared__ float4 tile[TILE];
    float d[KK]; int id[KK];
#pragma unroll
    for (int t=0;t<KK;t++){ d[t] = INFINITY; id[t] = 0x7FFFFFFF; }

    int base = s*CHUNK;
    for (int t0=0; t0<CHUNK; t0+=TILE){
        for (int i=threadIdx.x; i<TILE; i+=blockDim.x){
            int j = base + t0 + i;
            float cx = P[j], cy = P[NN+j], cz = P[2*NN+j];
            tile[i] = make_float4(cx, cy, cz, fmaf(cz,cz, fmaf(cy,cy, cx*cx)));
        }
        __syncthreads();
#pragma unroll 4
        for (int i=0;i<TILE;i++){
            float4 c = tile[i];
            float dot = fmaf(qz,c.z, fmaf(qy,c.y, qx*c.x));
            float dd  = fmaf(-2.f, dot, qs + c.w);
            if (dd < d[KK-1]){
                int jj = base + t0 + i;
#pragma unroll
                for (int u=KK-1; u>=0; --u){
                    bool sh = (u>0) && (dd < d[u-1]);
                    if (sh){ d[u] = d[u-1]; id[u] = id[u-1]; }
                    else   { d[u] = dd;     id[u] = jj; break; }
                }
            }
        }
        __syncthreads();
    }
    size_t o = ((size_t)(b*SPLITS+s)*NN + n)*KK;
#pragma unroll
    for (int t=0;t<KK;t++){ g_knn_d[o+t] = d[t]; g_knn_i[o+t] = id[t]; }
}

// ------------- merge splits, emit x = [center, nbr-center], x-moments -------
__global__ void __launch_bounds__(256) k_merge(const float* __restrict__ pts){
    int b = blockIdx.y;
    int n = blockIdx.x*blockDim.x + threadIdx.x;
    int lane = threadIdx.x & 31;

    float d[KK]; int id[KK];
#pragma unroll
    for (int t=0;t<KK;t++){ d[t] = INFINITY; id[t] = 0x7FFFFFFF; }

    for (int s=0;s<SPLITS;s++){
        size_t o = ((size_t)(b*SPLITS+s)*NN + n)*KK;
#pragma unroll
        for (int t=0;t<KK;t++){
            float dd = g_knn_d[o+t]; int jj = g_knn_i[o+t];
            if (dd < d[KK-1]){
#pragma unroll
                for (int u=KK-1; u>=0; --u){
                    bool sh = (u>0) && (dd < d[u-1]);
                    if (sh){ d[u] = d[u-1]; id[u] = id[u-1]; }
                    else   { d[u] = dd;     id[u] = jj; break; }
                }
            }
        }
    }

    const float* P = pts + (size_t)b*3*NN;
    float qx = P[n], qy = P[NN+n], qz = P[2*NN+n];
    float mu[6]; float MM[21];
#pragma unroll
    for (int i=0;i<6;i++) mu[i] = 0.f;
#pragma unroll
    for (int i=0;i<21;i++) MM[i] = 0.f;

    size_t xb = (size_t)b*6*NK + (size_t)n*KK;
#pragma unroll
    for (int t=0;t<KK;t++){
        int j = id[t];
        float v[6];
        v[0]=qx; v[1]=qy; v[2]=qz;
        v[3]=P[j]-qx; v[4]=P[NN+j]-qy; v[5]=P[2*NN+j]-qz;
#pragma unroll
        for (int c=0;c<6;c++) g_x[xb + (size_t)c*NK + t] = v[c];
        int m=0;
#pragma unroll
        for (int i=0;i<6;i++){
            mu[i] += v[i];
#pragma unroll
            for (int j2=i;j2<6;j2++){ MM[m] = fmaf(v[i], v[j2], MM[m]); m++; }
        }
    }
#pragma unroll
    for (int i=0;i<6;i++){
        float r = mu[i];
#pragma unroll
        for (int o=16;o>0;o>>=1) r += __shfl_down_sync(0xFFFFFFFFu, r, o);
        if (lane==0) atomicAdd(&g_mu[b*6+i], r);
    }
#pragma unroll
    for (int i=0;i<21;i++){
        float r = MM[i];
#pragma unroll
        for (int o=16;o>0;o>>=1) r += __shfl_down_sync(0xFFFFFFFFu, r, o);
        if (lane==0) atomicAdd(&g_M[b*21+i], r);
    }
}

// -------- GN1 stats from moments: exact group mean/var of y1 = W0 x + b0 ----
__global__ void k_gn1(const float* __restrict__ w0, const float* __restrict__ b0,
                      const float* __restrict__ gm, const float* __restrict__ be){
    int t = threadIdx.x;
    if (t >= 32) return;
    int b = t >> 3, g = t & 7;
    const float inv = 1.f/(float)NK;
    float mu[6], M[21];
#pragma unroll
    for (int i=0;i<6;i++)  mu[i] = g_mu[b*6+i]*inv;
#pragma unroll
    for (int i=0;i<21;i++) M[i]  = g_M[b*21+i]*inv;

    float Ey[4], Ey2[4];
#pragma unroll
    for (int cc=0;cc<4;cc++){
        int c = g*4+cc;
        float w[6];
#pragma unroll
        for (int i=0;i<6;i++) w[i] = w0[c*6+i];
        float lin = 0.f;
#pragma unroll
        for (int i=0;i<6;i++) lin = fmaf(w[i], mu[i], lin);
        float quad = 0.f; int m=0;
#pragma unroll
        for (int i=0;i<6;i++){
#pragma unroll
            for (int j=i;j<6;j++){
                float term = w[i]*w[j]*M[m];
                quad += (i==j) ? term : 2.f*term;
                m++;
            }
        }
        float bb = b0[c];
        Ey[cc]  = lin + bb;
        Ey2[cc] = quad + 2.f*bb*lin + bb*bb;
    }
    float mg = 0.25f*(Ey[0]+Ey[1]+Ey[2]+Ey[3]);
    float e2 = 0.25f*(Ey2[0]+Ey2[1]+Ey2[2]+Ey2[3]);
    float v  = e2 - mg*mg;
    float rs = rsqrtf(v + 1e-5f);
#pragma unroll
    for (int cc=0;cc<4;cc++){
        int c = g*4+cc;
        float A = gm[c]*rs;
        g_A1[b*32+c] = A;
        g_B1[b*32+c] = fmaf(A, b0[c], be[c] - mg*rs*gm[c]);
    }
}

// ----- fused pass 2: y1 -> GN1+ELU -> y2 ; stats + max/min over N -----------
__global__ void __launch_bounds__(640) k_pass2(const float* __restrict__ w0,
                                               const float* __restrict__ w1,
                                               const float* __restrict__ b1){
    __shared__ float sW0[32*6];
    __shared__ float sA[32], sB[32];
    __shared__ float sW1[64*32];
    __shared__ float sB1[64];
    __shared__ float sSum[64], sSq[64];

    int b = blockIdx.y;
    int tid = threadIdx.x;
    int k = tid >> 5;       // warp id 0..19 == neighbor slot
    int lane = tid & 31;
    int n = blockIdx.x*32 + lane;

    for (int i=tid;i<192;i+=640) sW0[i] = w0[i];
    for (int i=tid;i<32;i+=640){ sA[i] = g_A1[b*32+i]; sB[i] = g_B1[b*32+i]; }
    for (int i=tid;i<2048;i+=640) sW1[i] = w1[i];
    for (int i=tid;i<64;i+=640){ sB1[i] = b1[i]; sSum[i] = 0.f; sSq[i] = 0.f; }
    __syncthreads();

    size_t p = (size_t)b*6*NK + (size_t)n*KK + k;
    float x0 = g_x[p];
    float x1 = g_x[p +   (size_t)NK];
    float x2 = g_x[p + 2*(size_t)NK];
    float x3 = g_x[p + 3*(size_t)NK];
    float x4 = g_x[p + 4*(size_t)NK];
    float x5 = g_x[p + 5*(size_t)NK];

    float z[32];
#pragma unroll
    for (int c=0;c<32;c++){
        const float* w = &sW0[c*6];
        float acc = w[0]*x0;
        acc = fmaf(w[1],x1,acc); acc = fmaf(w[2],x2,acc);
        acc = fmaf(w[3],x3,acc); acc = fmaf(w[4],x4,acc);
        acc = fmaf(w[5],x5,acc);
        z[c] = elu1(fmaf(sA[c], acc, sB[c]));
    }

#pragma unroll 1
    for (int c=0;c<64;c++){
        const float* w = &sW1[c*32];
        float acc = sB1[c];
#pragma unroll
        for (int j=0;j<32;j++) acc = fmaf(w[j], z[j], acc);
        float mx = acc, mn = acc, sm = acc, sq = acc*acc;
#pragma unroll
        for (int o=16;o>0;o>>=1){
            mx = fmaxf(mx, __shfl_xor_sync(0xFFFFFFFFu, mx, o));
            mn = fminf(mn, __shfl_xor_sync(0xFFFFFFFFu, mn, o));
            sm += __shfl_xor_sync(0xFFFFFFFFu, sm, o);
            sq += __shfl_xor_sync(0xFFFFFFFFu, sq, o);
        }
        if (lane==0){
            atomicMax(&g_max2[(b*64+c)*KK + k], fenc(mx));
            atomicMin(&g_min2[(b*64+c)*KK + k], fenc(mn));
            atomicAdd(&sSum[c], sm);
            atomicAdd(&sSq[c],  sq);
        }
    }
    __syncthreads();
    if (tid < 64){
        atomicAdd(&g_sum2[b*64+tid], sSum[tid]);
        atomicAdd(&g_sq2[b*64+tid],  sSq[tid]);
    }
}

// ------ tail 1: GN2 apply on max/min -> ELU -> x3 -> y3 (64->512) + stats ---
__global__ void __launch_bounds__(512) k_tail1(const float* __restrict__ g2,
                                               const float* __restrict__ be2,
                                               const float* __restrict__ w2,
                                               const float* __restrict__ b2){
    int b = blockIdx.x;
    int tid = threadIdx.x;
    __shared__ float sA2[64], sB2[64];
    __shared__ float sx3[64*21];
    __shared__ float s3[8], q3[8];

    if (tid < 8){
        float sg=0.f, qg=0.f;
#pragma unroll
        for (int i=0;i<8;i++){ sg += g_sum2[b*64+tid*8+i]; qg += g_sq2[b*64+tid*8+i]; }
        float cnt = 8.f*(float)NK;
        float m = sg/cnt;
        float v = qg/cnt - m*m;
        float rs = rsqrtf(v + 1e-5f);
#pragma unroll
        for (int i=0;i<8;i++){
            int c = tid*8+i;
            float A = g2[c]*rs;
            sA2[c] = A; sB2[c] = be2[c] - m*A;
        }
        s3[tid] = 0.f; q3[tid] = 0.f;
    }
    __syncthreads();

    for (int i=tid; i<64*KK; i+=512){
        int c = i/KK, k = i%KK;
        float fmx = fdec(g_max2[(b*64+c)*KK+k]);
        float fmn = fdec(g_min2[(b*64+c)*KK+k]);
        float val = (sA2[c] >= 0.f) ? fmx : fmn;     // GN2+ELU monotone per sign(gamma)
        sx3[c*21+k] = elu1(fmaf(sA2[c], val, sB2[c]));
    }
    __syncthreads();

    for (int o=tid; o<512*KK; o+=512){
        int c = o/KK, k = o%KK;
        float acc = b2[c];
        const float* w = &w2[c*64];
#pragma unroll
        for (int j=0;j<64;j++) acc = fmaf(w[j], sx3[j*21+k], acc);
        g_y3[(size_t)b*512*KK + o] = acc;
        atomicAdd(&s3[c>>6], acc);
        atomicAdd(&q3[c>>6], acc*acc);
    }
    __syncthreads();
    if (tid < 8){ g_s3[b*8+tid] = s3[tid]; g_q3[b*8+tid] = q3[tid]; }
}

// ------ tail 2: z3 = ELU(GN3(y3)) smem-cached; y4 (512->1024) + GN4 stats ---
__global__ void __launch_bounds__(256) k_tail2(const float* __restrict__ g3c,
                                               const float* __restrict__ be3,
                                               const float* __restrict__ w3,
                                               const float* __restrict__ b3){
    __shared__ float sz[512*KK];        // 40 KB
    __shared__ float sm3[8], sr3[8];
    __shared__ float s4[8], q4[8];

    int blk = blockIdx.x;               // 80 blocks per batch
    int b = blk/80;
    int tid = threadIdx.x;

    if (tid < 8){
        float cnt = 64.f*(float)KK;
        float m = g_s3[b*8+tid]/cnt;
        float v = g_q3[b*8+tid]/cnt - m*m;
        sm3[tid] = m; sr3[tid] = rsqrtf(v + 1e-5f);
        s4[tid] = 0.f; q4[tid] = 0.f;
    }
    __syncthreads();

    for (int i=tid; i<512*KK; i+=256){
        int c = i/KK;
        int g = c>>6;
        float y = g_y3[(size_t)b*512*KK + i];
        float A = g3c[c]*sr3[g];
        sz[i] = elu1(fmaf(A, y, be3[c] - sm3[g]*A));
    }
    __syncthreads();

    int o = blk*256 + tid;              // global over BB*1024*KK
    int r = o - b*1024*KK;
    int c4 = r/KK, k = r%KK;
    float acc = b3[c4];
    const float* w = &w3[(size_t)c4*512];
#pragma unroll 8
    for (int j=0;j<512;j++) acc = fmaf(w[j], sz[j*KK+k], acc);
    g_y4[o] = acc;
    atomicAdd(&s4[c4>>7], acc);
    atomicAdd(&q4[c4>>7], acc*acc);
    __syncthreads();
    if (tid < 8){
        atomicAdd(&g_s4[b*8+tid], s4[tid]);
        atomicAdd(&g_q4[b*8+tid], q4[tid]);
    }
}

// ----------------------------- finalize -------------------------------------
__global__ void k_fin(const float* __restrict__ g4, const float* __restrict__ be4,
                      float* __restrict__ out){
    int o = blockIdx.x*256 + threadIdx.x;
    if (o >= BB*1024*KK) return;
    int b = o/(1024*KK);
    int r = o - b*1024*KK;
    int c = r/KK;
    int g = c>>7;
    float cnt = 128.f*(float)KK;
    float m = g_s4[b*8+g]/cnt;
    float v = g_q4[b*8+g]/cnt - m*m;
    float rs = rsqrtf(v + 1e-5f);
    float A = g4[c]*rs;
    out[o] = elu1(fmaf(A, g_y4[o], be4[c] - m*A));
}

// -----------------------------------------------------------------------------
extern "C" void kernel_launch(void* const* d_in, const int* in_sizes, int n_in,
                              void* d_out, int out_size){
    const float* pts  = (const float*)d_in[0];
    const float* p1w0 = (const float*)d_in[1];
    const float* p1b0 = (const float*)d_in[2];
    const float* p1g0 = (const float*)d_in[3];
    const float* p1be0= (const float*)d_in[4];
    const float* p1w1 = (const float*)d_in[5];
    const float* p1b1 = (const float*)d_in[6];
    const float* p1g1 = (const float*)d_in[7];
    const float* p1be1= (const float*)d_in[8];
    const float* p2w0 = (const float*)d_in[9];
    const float* p2b0 = (const float*)d_in[10];
    const float* p2g0 = (const float*)d_in[11];
    const float* p2be0= (const float*)d_in[12];
    const float* p2w1 = (const float*)d_in[13];
    const float* p2b1 = (const float*)d_in[14];
    const float* p2g1 = (const float*)d_in[15];
    const float* p2be1= (const float*)d_in[16];
    float* out = (float*)d_out;

    k_init<<<20, 256>>>();
    k_knn<<<dim3(NN/128, SPLITS, BB), 128>>>(pts);
    k_merge<<<dim3(NN/256, BB), 256>>>(pts);
    k_gn1<<<1, 32>>>(p1w0, p1b0, p1g0, p1be0);
    k_pass2<<<dim3(NN/32, BB), 640>>>(p1w0, p1w1, p1b1);
    k_tail1<<<BB, 512>>>(p1g1, p1be1, p2w0, p2b0);
    k_tail2<<<BB*80, 256>>>(p2g0, p2be0, p2w1, p2b1);
    k_fin<<<(BB*1024*KK + 255)/256, 256>>>(p2g1, p2be1, out);
}

// round 2
// speedup vs baseline: 4.2769x; 4.2769x over previous
#include <cuda_runtime.h>
#include <math.h>
#include <stdint.h>

#define BB 4
#define NN 8192
#define KK 20
#define NK (NN*KK)
#define KN ((size_t)KK*NN)

// ------------- scratch (device globals; no allocation allowed) -------------
__device__ float4   g_p4[BB*NN];                  // packed (x,y,z,|p|^2)
__device__ float    g_x[BB*6*NK];                 // [b][c][k][n]  (15.7 MB)
__device__ float    g_mu[BB*6];
__device__ float    g_M[BB*21];
__device__ float    g_A1[BB*32], g_B1[BB*32];
__device__ float    g_sum2[BB*64], g_sq2[BB*64];
__device__ unsigned g_max2[BB*64*KK], g_min2[BB*64*KK];
__device__ float    g_y3[BB*512*KK];
__device__ float    g_s3[BB*8], g_q3[BB*8];
__device__ float    g_y4[BB*1024*KK];
__device__ float    g_s4[BB*8], g_q4[BB*8];

__device__ __forceinline__ unsigned fenc(float f){
    unsigned u = __float_as_uint(f);
    return (u & 0x80000000u) ? ~u : (u | 0x80000000u);
}
__device__ __forceinline__ float fdec(unsigned u){
    u = (u & 0x80000000u) ? (u & 0x7FFFFFFFu) : ~u;
    return __uint_as_float(u);
}
__device__ __forceinline__ float elu1(float v){
    return v > 0.f ? v : expm1f(v);
}

// branchless sorted-insert: all static indices -> guaranteed registers
__device__ __forceinline__ void ins20(float (&d)[KK], int (&id)[KK], float dd, int jj){
    bool c[KK];
#pragma unroll
    for (int u=0; u<KK; u++) c[u] = dd < d[u];
#pragma unroll
    for (int u=KK-1; u>0; --u){
        d[u]  = c[u-1] ? d[u-1] : (c[u] ? dd : d[u]);
        id[u] = c[u-1] ? id[u-1] : (c[u] ? jj : id[u]);
    }
    if (c[0]){ d[0] = dd; id[0] = jj; }
}

// ------------------------------- init --------------------------------------
__global__ void k_init(){
    int i = blockIdx.x*blockDim.x + threadIdx.x;
    if (i < BB*64*KK){ g_max2[i] = 0u; g_min2[i] = 0xFFFFFFFFu; }
    if (i < BB*6)  g_mu[i] = 0.f;
    if (i < BB*21) g_M[i]  = 0.f;
    if (i < BB*64){ g_sum2[i] = 0.f; g_sq2[i] = 0.f; }
    if (i < BB*8){ g_s4[i] = 0.f; g_q4[i] = 0.f; }
}

// pack points into float4 (x,y,z,norm) for single-load candidate reads
__global__ void k_pack(const float* __restrict__ pts){
    int i = blockIdx.x*256 + threadIdx.x;
    if (i >= BB*NN) return;
    int b = i >> 13, n = i & (NN-1);
    const float* P = pts + (size_t)b*3*NN;
    float x = P[n], y = P[NN+n], z = P[2*NN+n];
    g_p4[i] = make_float4(x, y, z, fmaf(z,z, fmaf(y,y, x*x)));
}

// ---------------- KNN: single full scan per query, fused gather+moments ----
__global__ void __launch_bounds__(64) k_knn(){
    int b = blockIdx.y;
    int n = blockIdx.x*64 + threadIdx.x;
    int lane = threadIdx.x & 31;
    const float4* __restrict__ P4 = g_p4 + b*NN;

    float4 q = P4[n];
    float qx = q.x, qy = q.y, qz = q.z, qs = q.w;

    float d[KK]; int id[KK];
#pragma unroll
    for (int t=0;t<KK;t++){ d[t] = INFINITY; id[t] = 0x7FFFFFFF; }

#pragma unroll 8
    for (int j=0; j<NN; j++){
        float4 c = P4[j];                           // warp-uniform, L1-hit broadcast
        float dot = fmaf(qz,c.z, fmaf(qy,c.y, qx*c.x));
        float dd  = fmaf(-2.f, dot, qs + c.w);
        if (dd < d[KK-1]) ins20(d, id, dd, j);
    }

    // gather neighbors, write x = [center, nbr-center] in [b][c][k][n] layout
    float mu[6], MM[21];
#pragma unroll
    for (int i=0;i<6;i++)  mu[i] = 0.f;
#pragma unroll
    for (int i=0;i<21;i++) MM[i] = 0.f;

    size_t xb = (size_t)b*6*NK + n;
#pragma unroll
    for (int t=0;t<KK;t++){
        float4 nb = P4[id[t]];
        float v[6];
        v[0]=qx; v[1]=qy; v[2]=qz;
        v[3]=nb.x-qx; v[4]=nb.y-qy; v[5]=nb.z-qz;
#pragma unroll
        for (int c=0;c<6;c++)
            g_x[xb + ((size_t)c*KK + t)*NN] = v[c];   // coalesced across lanes
        int m=0;
#pragma unroll
        for (int i=0;i<6;i++){
            mu[i] += v[i];
#pragma unroll
            for (int j2=i;j2<6;j2++){ MM[m] = fmaf(v[i], v[j2], MM[m]); m++; }
        }
    }
#pragma unroll
    for (int i=0;i<6;i++){
        float r = mu[i];
#pragma unroll
        for (int o=16;o>0;o>>=1) r += __shfl_down_sync(0xFFFFFFFFu, r, o);
        if (lane==0) atomicAdd(&g_mu[b*6+i], r);
    }
#pragma unroll
    for (int i=0;i<21;i++){
        float r = MM[i];
#pragma unroll
        for (int o=16;o>0;o>>=1) r += __shfl_down_sync(0xFFFFFFFFu, r, o);
        if (lane==0) atomicAdd(&g_M[b*21+i], r);
    }
}

// -------- GN1 stats from moments: exact group mean/var of y1 = W0 x + b0 ----
__global__ void k_gn1(const float* __restrict__ w0, const float* __restrict__ b0,
                      const float* __restrict__ gm, const float* __restrict__ be){
    int t = threadIdx.x;
    if (t >= 32) return;
    int b = t >> 3, g = t & 7;
    const float inv = 1.f/(float)NK;
    float mu[6], M[21];
#pragma unroll
    for (int i=0;i<6;i++)  mu[i] = g_mu[b*6+i]*inv;
#pragma unroll
    for (int i=0;i<21;i++) M[i]  = g_M[b*21+i]*inv;

    float Ey[4], Ey2[4];
#pragma unroll
    for (int cc=0;cc<4;cc++){
        int c = g*4+cc;
        float w[6];
#pragma unroll
        for (int i=0;i<6;i++) w[i] = w0[c*6+i];
        float lin = 0.f;
#pragma unroll
        for (int i=0;i<6;i++) lin = fmaf(w[i], mu[i], lin);
        float quad = 0.f; int m=0;
#pragma unroll
        for (int i=0;i<6;i++){
#pragma unroll
            for (int j=i;j<6;j++){
                float term = w[i]*w[j]*M[m];
                quad += (i==j) ? term : 2.f*term;
                m++;
            }
        }
        float bb = b0[c];
        Ey[cc]  = lin + bb;
        Ey2[cc] = quad + 2.f*bb*lin + bb*bb;
    }
    float mg = 0.25f*(Ey[0]+Ey[1]+Ey[2]+Ey[3]);
    float e2 = 0.25f*(Ey2[0]+Ey2[1]+Ey2[2]+Ey2[3]);
    float v  = e2 - mg*mg;
    float rs = rsqrtf(v + 1e-5f);
#pragma unroll
    for (int cc=0;cc<4;cc++){
        int c = g*4+cc;
        float A = gm[c]*rs;
        g_A1[b*32+c] = A;
        g_B1[b*32+c] = fmaf(A, b0[c], be[c] - mg*rs*gm[c]);
    }
}

// ----- fused pass 2: y1 -> GN1+ELU -> y2 ; stats + max/min over N -----------
__global__ void __launch_bounds__(640) k_pass2(const float* __restrict__ w0,
                                               const float* __restrict__ w1,
                                               const float* __restrict__ b1){
    __shared__ float sW0[192];
    __shared__ float sA[32], sB[32];
    __shared__ float sW1[2048];
    __shared__ float sB1[64];
    __shared__ float sMx[64*KK], sMn[64*KK];       // warp-exclusive accumulators
    __shared__ float sPS[64*KK], sPQ[64*KK];

    int b = blockIdx.y;
    int tid = threadIdx.x;
    int k = tid >> 5;       // warp id 0..19 == neighbor slot
    int lane = tid & 31;

    for (int i=tid;i<192;i+=640) sW0[i] = w0[i];
    for (int i=tid;i<32;i+=640){ sA[i] = g_A1[b*32+i]; sB[i] = g_B1[b*32+i]; }
    for (int i=tid;i<2048;i+=640) sW1[i] = w1[i];
    for (int i=tid;i<64;i+=640) sB1[i] = b1[i];
    __syncthreads();

    for (int nt=0; nt<4; nt++){
        int n = blockIdx.x*128 + nt*32 + lane;
        size_t base = ((size_t)b*6*KK + k)*NN + n;
        float x0 = g_x[base];
        float x1 = g_x[base +   KN];
        float x2 = g_x[base + 2*KN];
        float x3 = g_x[base + 3*KN];
        float x4 = g_x[base + 4*KN];
        float x5 = g_x[base + 5*KN];

        float z[32];
#pragma unroll
        for (int c=0;c<32;c++){
            const float* w = &sW0[c*6];
            float acc = w[0]*x0;
            acc = fmaf(w[1],x1,acc); acc = fmaf(w[2],x2,acc);
            acc = fmaf(w[3],x3,acc); acc = fmaf(w[4],x4,acc);
            acc = fmaf(w[5],x5,acc);
            z[c] = elu1(fmaf(sA[c], acc, sB[c]));
        }

#pragma unroll 1
        for (int c=0;c<64;c++){
            const float* w = &sW1[c*32];
            float acc = sB1[c];
#pragma unroll
            for (int j=0;j<32;j++) acc = fmaf(w[j], z[j], acc);
            float mx = acc, mn = acc, sm = acc, sq = acc*acc;
#pragma unroll
            for (int o=16;o>0;o>>=1){
                mx = fmaxf(mx, __shfl_xor_sync(0xFFFFFFFFu, mx, o));
                mn = fminf(mn, __shfl_xor_sync(0xFFFFFFFFu, mn, o));
                sm += __shfl_xor_sync(0xFFFFFFFFu, sm, o);
                sq += __shfl_xor_sync(0xFFFFFFFFu, sq, o);
            }
            if (lane==0){
                int s = c*KK + k;                   // warp k exclusively owns [*,k]
                if (nt==0){ sMx[s]=mx; sMn[s]=mn; sPS[s]=sm; sPQ[s]=sq; }
                else {
                    sMx[s] = fmaxf(sMx[s], mx);
                    sMn[s] = fminf(sMn[s], mn);
                    sPS[s] += sm;
                    sPQ[s] += sq;
                }
            }
        }
    }
    __syncthreads();

    for (int i=tid; i<64*KK; i+=640){
        atomicMax(&g_max2[b*64*KK + i], fenc(sMx[i]));
        atomicMin(&g_min2[b*64*KK + i], fenc(sMn[i]));
    }
    if (tid < 64){
        float s=0.f, qq=0.f;
#pragma unroll
        for (int t=0;t<KK;t++){ s += sPS[tid*KK+t]; qq += sPQ[tid*KK+t]; }
        atomicAdd(&g_sum2[b*64+tid], s);
        atomicAdd(&g_sq2[b*64+tid],  qq);
    }
}

// ------ tail 1: GN2 apply on max/min -> ELU -> x3 -> y3 (64->512) + stats ---
__global__ void __launch_bounds__(512) k_tail1(const float* __restrict__ g2,
                                               const float* __restrict__ be2,
                                               const float* __restrict__ w2,
                                               const float* __restrict__ b2){
    int b = blockIdx.x;
    int tid = threadIdx.x;
    __shared__ float sA2[64], sB2[64];
    __shared__ float sx3[64*21];
    __shared__ float s3[8], q3[8];

    if (tid < 8){
        float sg=0.f, qg=0.f;
#pragma unroll
        for (int i=0;i<8;i++){ sg += g_sum2[b*64+tid*8+i]; qg += g_sq2[b*64+tid*8+i]; }
        float cnt = 8.f*(float)NK;
        float m = sg/cnt;
        float v = qg/cnt - m*m;
        float rs = rsqrtf(v + 1e-5f);
#pragma unroll
        for (int i=0;i<8;i++){
            int c = tid*8+i;
            float A = g2[c]*rs;
            sA2[c] = A; sB2[c] = be2[c] - m*A;
        }
        s3[tid] = 0.f; q3[tid] = 0.f;
    }
    __syncthreads();

    for (int i=tid; i<64*KK; i+=512){
        int c = i/KK, k = i%KK;
        float fmx = fdec(g_max2[(b*64+c)*KK+k]);
        float fmn = fdec(g_min2[(b*64+c)*KK+k]);
        float val = (sA2[c] >= 0.f) ? fmx : fmn;
        sx3[c*21+k] = elu1(fmaf(sA2[c], val, sB2[c]));
    }
    __syncthreads();

    for (int o=tid; o<512*KK; o+=512){
        int c = o/KK, k = o%KK;
        float acc = b2[c];
        const float* w = &w2[c*64];
#pragma unroll
        for (int j=0;j<64;j++) acc = fmaf(w[j], sx3[j*21+k], acc);
        g_y3[(size_t)b*512*KK + o] = acc;
        atomicAdd(&s3[c>>6], acc);
        atomicAdd(&q3[c>>6], acc*acc);
    }
    __syncthreads();
    if (tid < 8){ g_s3[b*8+tid] = s3[tid]; g_q3[b*8+tid] = q3[tid]; }
}

// ------ tail 2: z3 = ELU(GN3(y3)) smem-cached; y4 (512->1024) + GN4 stats ---
__global__ void __launch_bounds__(256) k_tail2(const float* __restrict__ g3c,
                                               const float* __restrict__ be3,
                                               const float* __restrict__ w3,
                                               const float* __restrict__ b3){
    __shared__ float sz[512*KK];
    __shared__ float sm3[8], sr3[8];
    __shared__ float s4[8], q4[8];

    int blk = blockIdx.x;
    int b = blk/80;
    int tid = threadIdx.x;

    if (tid < 8){
        float cnt = 64.f*(float)KK;
        float m = g_s3[b*8+tid]/cnt;
        float v = g_q3[b*8+tid]/cnt - m*m;
        sm3[tid] = m; sr3[tid] = rsqrtf(v + 1e-5f);
        s4[tid] = 0.f; q4[tid] = 0.f;
    }
    __syncthreads();

    for (int i=tid; i<512*KK; i+=256){
        int c = i/KK;
        int g = c>>6;
        float y = g_y3[(size_t)b*512*KK + i];
        float A = g3c[c]*sr3[g];
        sz[i] = elu1(fmaf(A, y, be3[c] - sm3[g]*A));
    }
    __syncthreads();

    int o = blk*256 + tid;
    int r = o - b*1024*KK;
    int c4 = r/KK, k = r%KK;
    float acc = b3[c4];
    const float* w = &w3[(size_t)c4*512];
#pragma unroll 8
    for (int j=0;j<512;j++) acc = fmaf(w[j], sz[j*KK+k], acc);
    g_y4[o] = acc;
    atomicAdd(&s4[c4>>7], acc);
    atomicAdd(&q4[c4>>7], acc*acc);
    __syncthreads();
    if (tid < 8){
        atomicAdd(&g_s4[b*8+tid], s4[tid]);
        atomicAdd(&g_q4[b*8+tid], q4[tid]);
    }
}

// ----------------------------- finalize -------------------------------------
__global__ void k_fin(const float* __restrict__ g4, const float* __restrict__ be4,
                      float* __restrict__ out){
    int o = blockIdx.x*256 + threadIdx.x;
    if (o >= BB*1024*KK) return;
    int b = o/(1024*KK);
    int r = o - b*1024*KK;
    int c = r/KK;
    int g = c>>7;
    float cnt = 128.f*(float)KK;
    float m = g_s4[b*8+g]/cnt;
    float v = g_q4[b*8+g]/cnt - m*m;
    float rs = rsqrtf(v + 1e-5f);
    float A = g4[c]*rs;
    out[o] = elu1(fmaf(A, g_y4[o], be4[c] - m*A));
}

// -----------------------------------------------------------------------------
extern "C" void kernel_launch(void* const* d_in, const int* in_sizes, int n_in,
                              void* d_out, int out_size){
    const float* pts  = (const float*)d_in[0];
    const float* p1w0 = (const float*)d_in[1];
    const float* p1b0 = (const float*)d_in[2];
    const float* p1g0 = (const float*)d_in[3];
    const float* p1be0= (const float*)d_in[4];
    const float* p1w1 = (const float*)d_in[5];
    const float* p1b1 = (const float*)d_in[6];
    const float* p1g1 = (const float*)d_in[7];
    const float* p1be1= (const float*)d_in[8];
    const float* p2w0 = (const float*)d_in[9];
    const float* p2b0 = (const float*)d_in[10];
    const float* p2g0 = (const float*)d_in[11];
    const float* p2be0= (const float*)d_in[12];
    const float* p2w1 = (const float*)d_in[13];
    const float* p2b1 = (const float*)d_in[14];
    const float* p2g1 = (const float*)d_in[15];
    const float* p2be1= (const float*)d_in[16];
    float* out = (float*)d_out;

    k_init<<<20, 256>>>();
    k_pack<<<(BB*NN+255)/256, 256>>>(pts);
    k_knn<<<dim3(NN/64, BB), 64>>>();
    k_gn1<<<1, 32>>>(p1w0, p1b0, p1g0, p1be0);
    k_pass2<<<dim3(NN/128, BB), 640>>>(p1w0, p1w1, p1b1);
    k_tail1<<<BB, 512>>>(p1g1, p1be1, p2w0, p2b0);
    k_tail2<<<BB*80, 256>>>(p2g0, p2be0, p2w1, p2b1);
    k_fin<<<(BB*1024*KK + 255)/256, 256>>>(p2g1, p2be1, out);
}

// round 3
// speedup vs baseline: 13.5048x; 3.1576x over previous
#include <cuda_runtime.h>
#include <math.h>
#include <stdint.h>

#define BB 4
#define NN 8192
#define KK 20
#define NK (NN*KK)
#define KN ((size_t)KK*NN)

// ------------- scratch (device globals; no allocation allowed) -------------
__device__ float4   g_p4[BB*NN];                  // packed (x,y,z,|p|^2)
__device__ float    g_x[BB*6*NK];                 // [b][c][k][n]
__device__ float    g_mu[BB*6];
__device__ float    g_M[BB*21];
__device__ float    g_A1[BB*32], g_B1[BB*32];
__device__ float    g_sum2[BB*64], g_sq2[BB*64];
__device__ unsigned g_max2[BB*64*KK], g_min2[BB*64*KK];
__device__ float    g_y3[BB*512*KK];
__device__ float    g_s3[BB*8], g_q3[BB*8];
__device__ float    g_y4[BB*1024*KK];
__device__ float    g_s4[BB*8], g_q4[BB*8];

__device__ __forceinline__ unsigned fenc(float f){
    unsigned u = __float_as_uint(f);
    return (u & 0x80000000u) ? ~u : (u | 0x80000000u);
}
__device__ __forceinline__ float fdec(unsigned u){
    u = (u & 0x80000000u) ? (u & 0x7FFFFFFFu) : ~u;
    return __uint_as_float(u);
}
__device__ __forceinline__ float elu1(float v){
    return v > 0.f ? v : expm1f(v);
}

typedef unsigned long long ull;
#define FMA2(d,a,b,c) asm("fma.rn.f32x2 %0, %1, %2, %3;" : "=l"(d) : "l"(a), "l"(b), "l"(c))
#define MUL2(d,a,b)   asm("mul.rn.f32x2 %0, %1, %2;"     : "=l"(d) : "l"(a), "l"(b))
__device__ __forceinline__ ull pk2(float lo, float hi){
    ull r; asm("mov.b64 %0, {%1,%2};" : "=l"(r) : "f"(lo), "f"(hi)); return r;
}
__device__ __forceinline__ void up2(ull v, float& lo, float& hi){
    asm("mov.b64 {%0,%1}, %2;" : "=f"(lo), "=f"(hi) : "l"(v));
}
__device__ __forceinline__ ull elu2(ull v){
    float lo, hi; up2(v, lo, hi);
    return pk2(elu1(lo), elu1(hi));
}

// ------------------------------- init --------------------------------------
__global__ void k_init(){
    int i = blockIdx.x*blockDim.x + threadIdx.x;
    if (i < BB*64*KK){ g_max2[i] = 0u; g_min2[i] = 0xFFFFFFFFu; }
    if (i < BB*6)  g_mu[i] = 0.f;
    if (i < BB*21) g_M[i]  = 0.f;
    if (i < BB*64){ g_sum2[i] = 0.f; g_sq2[i] = 0.f; }
    if (i < BB*8){ g_s3[i]=0.f; g_q3[i]=0.f; g_s4[i]=0.f; g_q4[i]=0.f; }
}

// pack points into float4 (x,y,z,norm)
__global__ void k_pack(const float* __restrict__ pts){
    int i = blockIdx.x*256 + threadIdx.x;
    if (i >= BB*NN) return;
    int b = i >> 13, n = i & (NN-1);
    const float* P = pts + (size_t)b*3*NN;
    float x = P[n], y = P[NN+n], z = P[2*NN+n];
    g_p4[i] = make_float4(x, y, z, fmaf(z,z, fmaf(y,y, x*x)));
}

// ------------- KNN: warp per query, warp-distributed sorted top-20 ---------
__global__ void __launch_bounds__(256) k_knn(){
    int b = blockIdx.y;
    int tid = threadIdx.x;
    int lane = tid & 31;
    int n = blockIdx.x*8 + (tid >> 5);
    const float4* __restrict__ P4 = g_p4 + b*NN;

    __shared__ float sAcc[27];
    if (tid < 27) sAcc[tid] = 0.f;
    __syncthreads();

    float4 q = P4[n];
    float qx=q.x, qy=q.y, qz=q.z, qs=q.w;

    // distributed list: lane i<20 holds i-th best (df ascending, stable by idx)
    float df = INFINITY; int ji = 0x7FFFFFFF;
    float th = INFINITY;                     // current 20th-best distance

#pragma unroll 4
    for (int t=0; t<NN/32; t++){
        int j = t*32 + lane;
        float4 c = P4[j];
        float dot = fmaf(qz,c.z, fmaf(qy,c.y, qx*c.x));
        float dd  = fmaf(-2.f, dot, qs + c.w);
        unsigned bal = __ballot_sync(0xFFFFFFFFu, dd < th);
        while (bal){
            int s = __ffs(bal) - 1; bal &= bal - 1;
            float ddv = __shfl_sync(0xFFFFFFFFu, dd, s);
            if (ddv < th){
                int jv = t*32 + s;
                // position = #elements with d <= ddv  (all list idx < jv -> stable)
                int p = __popc(__ballot_sync(0xFFFFFFFFu, df <= ddv) & 0xFFFFFu);
                float dup = __shfl_up_sync(0xFFFFFFFFu, df, 1);
                int   iup = __shfl_up_sync(0xFFFFFFFFu, ji, 1);
                if (lane > p){ df = dup; ji = iup; }
                else if (lane == p){ df = ddv; ji = jv; }
                th = __shfl_sync(0xFFFFFFFFu, df, 19);
            }
        }
    }

    // gather + write x in [b][c][k][n] layout; k = lane
    float v0=0.f,v1=0.f,v2=0.f,v3=0.f,v4=0.f,v5=0.f;
    if (lane < KK){
        float4 nb = P4[ji];
        v0=qx; v1=qy; v2=qz;
        v3=nb.x-qx; v4=nb.y-qy; v5=nb.z-qz;
        size_t o = ((size_t)(b*6)*KK + lane)*NN + n;
        g_x[o       ] = v0;
        g_x[o +   KN] = v1;
        g_x[o + 2*KN] = v2;
        g_x[o + 3*KN] = v3;
        g_x[o + 4*KN] = v4;
        g_x[o + 5*KN] = v5;
    }

    // moments: only diff-dependent sums need reduction (9 butterflies)
    float S0=v3, S1=v4, S2=v5;
    float P00=v3*v3, P01=v3*v4, P02=v3*v5, P11=v4*v4, P12=v4*v5, P22=v5*v5;
#pragma unroll
    for (int o=16;o>0;o>>=1){
        S0 += __shfl_xor_sync(0xFFFFFFFFu,S0,o);
        S1 += __shfl_xor_sync(0xFFFFFFFFu,S1,o);
        S2 += __shfl_xor_sync(0xFFFFFFFFu,S2,o);
        P00+= __shfl_xor_sync(0xFFFFFFFFu,P00,o);
        P01+= __shfl_xor_sync(0xFFFFFFFFu,P01,o);
        P02+= __shfl_xor_sync(0xFFFFFFFFu,P02,o);
        P11+= __shfl_xor_sync(0xFFFFFFFFu,P11,o);
        P12+= __shfl_xor_sync(0xFFFFFFFFu,P12,o);
        P22+= __shfl_xor_sync(0xFFFFFFFFu,P22,o);
    }
    // 27 moment values: mu[6], then upper-tri M (i<=j) in row order
    float K20 = 20.f;
    float m[27];
    m[0]=K20*qx; m[1]=K20*qy; m[2]=K20*qz; m[3]=S0; m[4]=S1; m[5]=S2;
    // row i=0 (qx): qx*qx*20, qx*qy*20, qx*qz*20, qx*S0, qx*S1, qx*S2
    m[6]=K20*qx*qx; m[7]=K20*qx*qy; m[8]=K20*qx*qz; m[9]=qx*S0; m[10]=qx*S1; m[11]=qx*S2;
    m[12]=K20*qy*qy; m[13]=K20*qy*qz; m[14]=qy*S0; m[15]=qy*S1; m[16]=qy*S2;
    m[17]=K20*qz*qz; m[18]=qz*S0; m[19]=qz*S1; m[20]=qz*S2;
    m[21]=P00; m[22]=P01; m[23]=P02;
    m[24]=P11; m[25]=P12;
    m[26]=P22;
    float mval = m[0];
#pragma unroll
    for (int i=1;i<27;i++) if (lane==i) mval = m[i];
    if (lane < 27) atomicAdd(&sAcc[lane], mval);

    __syncthreads();
    if (tid < 27){
        if (tid < 6) atomicAdd(&g_mu[b*6+tid], sAcc[tid]);
        else         atomicAdd(&g_M[b*21+tid-6], sAcc[tid]);
    }
}

// -------- GN1 stats from moments: exact group mean/var of y1 = W0 x + b0 ----
__global__ void k_gn1(const float* __restrict__ w0, const float* __restrict__ b0,
                      const float* __restrict__ gm, const float* __restrict__ be){
    int t = threadIdx.x;
    if (t >= 32) return;
    int b = t >> 3, g = t & 7;
    const float inv = 1.f/(float)NK;
    float mu[6], M[21];
#pragma unroll
    for (int i=0;i<6;i++)  mu[i] = g_mu[b*6+i]*inv;
#pragma unroll
    for (int i=0;i<21;i++) M[i]  = g_M[b*21+i]*inv;

    float Ey[4], Ey2[4];
#pragma unroll
    for (int cc=0;cc<4;cc++){
        int c = g*4+cc;
        float w[6];
#pragma unroll
        for (int i=0;i<6;i++) w[i] = w0[c*6+i];
        float lin = 0.f;
#pragma unroll
        for (int i=0;i<6;i++) lin = fmaf(w[i], mu[i], lin);
        float quad = 0.f; int mI=0;
#pragma unroll
        for (int i=0;i<6;i++){
#pragma unroll
            for (int j=i;j<6;j++){
                float term = w[i]*w[j]*M[mI];
                quad += (i==j) ? term : 2.f*term;
                mI++;
            }
        }
        float bb = b0[c];
        Ey[cc]  = lin + bb;
        Ey2[cc] = quad + 2.f*bb*lin + bb*bb;
    }
    float mg = 0.25f*(Ey[0]+Ey[1]+Ey[2]+Ey[3]);
    float e2 = 0.25f*(Ey2[0]+Ey2[1]+Ey2[2]+Ey2[3]);
    float v  = e2 - mg*mg;
    float rs = rsqrtf(v + 1e-5f);
#pragma unroll
    for (int cc=0;cc<4;cc++){
        int c = g*4+cc;
        float A = gm[c]*rs;
        g_A1[b*32+c] = A;
        g_B1[b*32+c] = fmaf(A, b0[c], be[c] - mg*rs*gm[c]);
    }
}

// ----- fused pass 2: packed f32x2, smem-transpose reductions ---------------
// block = 320 threads (10 warps); warp w handles k = w and w+10; 64 n per block
__global__ void __launch_bounds__(320) k_pass2(const float* __restrict__ w0,
                                               const float* __restrict__ w1,
                                               const float* __restrict__ b1){
    __shared__ ull  sW0d[192];
    __shared__ ull  sAd[32], sBd[32];
    __shared__ float sW1[2048];
    __shared__ ull  sB1d[64];
    __shared__ ull  buf[10][4][34];
    __shared__ float sMx[64*KK], sMn[64*KK];
    __shared__ float sPS[64], sPQ[64];

    int b = blockIdx.y;
    int tid = threadIdx.x;
    int w = tid >> 5;
    int lane = tid & 31;

    for (int i=tid;i<192;i+=320){ float t = w0[i]; sW0d[i] = pk2(t,t); }
    for (int i=tid;i<32;i+=320){
        float a = g_A1[b*32+i], bb = g_B1[b*32+i];
        sAd[i] = pk2(a,a); sBd[i] = pk2(bb,bb);
    }
    for (int i=tid;i<2048;i+=320) sW1[i] = w1[i];
    for (int i=tid;i<64;i+=320){ float t=b1[i]; sB1d[i]=pk2(t,t); sPS[i]=0.f; sPQ[i]=0.f; }
    __syncthreads();

    int n0 = blockIdx.x*64 + lane*2;

    for (int ks=0; ks<2; ks++){
        int kk = w + ks*10;
        size_t base = ((size_t)(b*6)*KK + kk)*NN + n0;
        ull xp[6];
#pragma unroll
        for (int c6=0;c6<6;c6++){
            float2 t = *(const float2*)&g_x[base + (size_t)c6*KN];
            xp[c6] = pk2(t.x, t.y);
        }
        ull z2[32];
#pragma unroll
        for (int zc=0;zc<32;zc++){
            ull acc;
            MUL2(acc, sW0d[zc*6], xp[0]);
            FMA2(acc, sW0d[zc*6+1], xp[1], acc);
            FMA2(acc, sW0d[zc*6+2], xp[2], acc);
            FMA2(acc, sW0d[zc*6+3], xp[3], acc);
            FMA2(acc, sW0d[zc*6+4], xp[4], acc);
            FMA2(acc, sAd[zc], acc, sBd[zc]);   // note: fold x5 below? no -- keep 6 terms
            z2[zc] = acc;                        // placeholder, fixed just after
        }
        // redo properly with all 6 inputs then affine+elu (kept unrolled & simple)
#pragma unroll
        for (int zc=0;zc<32;zc++){
            ull acc;
            MUL2(acc, sW0d[zc*6], xp[0]);
            FMA2(acc, sW0d[zc*6+1], xp[1], acc);
            FMA2(acc, sW0d[zc*6+2], xp[2], acc);
            FMA2(acc, sW0d[zc*6+3], xp[3], acc);
            FMA2(acc, sW0d[zc*6+4], xp[4], acc);
            FMA2(acc, sW0d[zc*6+5], xp[5], acc);
            FMA2(acc, sAd[zc], acc, sBd[zc]);
            z2[zc] = elu2(acc);
        }

#pragma unroll 1
        for (int ch=0; ch<16; ch++){
            ull a0 = sB1d[ch*4+0], a1 = sB1d[ch*4+1], a2 = sB1d[ch*4+2], a3 = sB1d[ch*4+3];
            const float4* w1v0 = (const float4*)&sW1[(ch*4+0)*32];
            const float4* w1v1 = (const float4*)&sW1[(ch*4+1)*32];
            const float4* w1v2 = (const float4*)&sW1[(ch*4+2)*32];
            const float4* w1v3 = (const float4*)&sW1[(ch*4+3)*32];
#pragma unroll
            for (int j4=0;j4<8;j4++){
                float4 q0 = w1v0[j4], q1 = w1v1[j4], q2 = w1v2[j4], q3 = w1v3[j4];
                ull zj0 = z2[j4*4+0], zj1 = z2[j4*4+1], zj2 = z2[j4*4+2], zj3 = z2[j4*4+3];
                FMA2(a0, pk2(q0.x,q0.x), zj0, a0); FMA2(a1, pk2(q1.x,q1.x), zj0, a1);
                FMA2(a2, pk2(q2.x,q2.x), zj0, a2); FMA2(a3, pk2(q3.x,q3.x), zj0, a3);
                FMA2(a0, pk2(q0.y,q0.y), zj1, a0); FMA2(a1, pk2(q1.y,q1.y), zj1, a1);
                FMA2(a2, pk2(q2.y,q2.y), zj1, a2); FMA2(a3, pk2(q3.y,q3.y), zj1, a3);
                FMA2(a0, pk2(q0.z,q0.z), zj2, a0); FMA2(a1, pk2(q1.z,q1.z), zj2, a1);
                FMA2(a2, pk2(q2.z,q2.z), zj2, a2); FMA2(a3, pk2(q3.z,q3.z), zj2, a3);
                FMA2(a0, pk2(q0.w,q0.w), zj3, a0); FMA2(a1, pk2(q1.w,q1.w), zj3, a1);
                FMA2(a2, pk2(q2.w,q2.w), zj3, a2); FMA2(a3, pk2(q3.w,q3.w), zj3, a3);
            }
            buf[w][0][lane]=a0; buf[w][1][lane]=a1; buf[w][2][lane]=a2; buf[w][3][lane]=a3;
            __syncwarp();
            {
                int cc2 = lane >> 3, s = lane & 7;
                const ull* row = &buf[w][cc2][s*4];
                float f[8];
                up2(row[0], f[0], f[1]); up2(row[1], f[2], f[3]);
                up2(row[2], f[4], f[5]); up2(row[3], f[6], f[7]);
                float mx=f[0], mn=f[0], sm=f[0], sq=f[0]*f[0];
#pragma unroll
                for (int i=1;i<8;i++){
                    mx=fmaxf(mx,f[i]); mn=fminf(mn,f[i]);
                    sm+=f[i]; sq=fmaf(f[i],f[i],sq);
                }
#pragma unroll
                for (int o=1;o<8;o<<=1){
                    mx=fmaxf(mx,__shfl_xor_sync(0xFFFFFFFFu,mx,o));
                    mn=fminf(mn,__shfl_xor_sync(0xFFFFFFFFu,mn,o));
                    sm+=__shfl_xor_sync(0xFFFFFFFFu,sm,o);
                    sq+=__shfl_xor_sync(0xFFFFFFFFu,sq,o);
                }
                if (s==0){
                    int cg = ch*4 + cc2;
                    int idx = cg*KK + kk;
                    sMx[idx]=mx; sMn[idx]=mn;
                    atomicAdd(&sPS[cg], sm); atomicAdd(&sPQ[cg], sq);
                }
            }
            __syncwarp();
        }
    }
    __syncthreads();
    for (int i=tid;i<64*KK;i+=320){
        atomicMax(&g_max2[b*64*KK+i], fenc(sMx[i]));
        atomicMin(&g_min2[b*64*KK+i], fenc(sMn[i]));
    }
    if (tid<64){
        atomicAdd(&g_sum2[b*64+tid], sPS[tid]);
        atomicAdd(&g_sq2[b*64+tid],  sPQ[tid]);
    }
}

// ------ tail 1: GN2 on max/min -> ELU -> y3 (64->512); grid (KK, BB) -------
__global__ void __launch_bounds__(512) k_tail1(const float* __restrict__ g2,
                                               const float* __restrict__ be2,
                                               const float* __restrict__ w2,
                                               const float* __restrict__ b2){
    int b = blockIdx.y, kq = blockIdx.x;
    int tid = threadIdx.x;
    __shared__ float sx3[64];

    if (tid < 64){
        int c = tid, g = c>>3;
        float sg=0.f, qg=0.f;
#pragma unroll
        for (int i=0;i<8;i++){ sg += g_sum2[b*64+g*8+i]; qg += g_sq2[b*64+g*8+i]; }
        float cnt = 8.f*(float)NK;
        float m = sg/cnt;
        float v = qg/cnt - m*m;
        float rs = rsqrtf(v + 1e-5f);
        float A = g2[c]*rs, Bc = be2[c] - m*A;
        float fmx = fdec(g_max2[(b*64+c)*KK+kq]);
        float fmn = fdec(g_min2[(b*64+c)*KK+kq]);
        float val = (A >= 0.f) ? fmx : fmn;
        sx3[c] = elu1(fmaf(A, val, Bc));
    }
    __syncthreads();

    int c4 = tid;
    float acc = b2[c4];
    const float4* wv = (const float4*)&w2[c4*64];
#pragma unroll
    for (int j=0;j<16;j++){
        float4 q = wv[j];
        acc = fmaf(q.x, sx3[j*4+0], acc);
        acc = fmaf(q.y, sx3[j*4+1], acc);
        acc = fmaf(q.z, sx3[j*4+2], acc);
        acc = fmaf(q.w, sx3[j*4+3], acc);
    }
    g_y3[((size_t)b*512 + c4)*KK + kq] = acc;

    float sm = acc, sq = acc*acc;
#pragma unroll
    for (int o=16;o>0;o>>=1){
        sm += __shfl_xor_sync(0xFFFFFFFFu, sm, o);
        sq += __shfl_xor_sync(0xFFFFFFFFu, sq, o);
    }
    if ((tid&31)==0){
        atomicAdd(&g_s3[b*8 + (c4>>6)], sm);
        atomicAdd(&g_q3[b*8 + (c4>>6)], sq);
    }
}

// ------ tail 2: z3 = ELU(GN3(y3)) smem-cached; y4 (512->1024) + GN4 stats ---
__global__ void __launch_bounds__(256) k_tail2(const float* __restrict__ g3c,
                                               const float* __restrict__ be3,
                                               const float* __restrict__ w3,
                                               const float* __restrict__ b3){
    __shared__ float sz[512*KK];
    __shared__ float sm3[8], sr3[8];
    __shared__ float s4[8], q4[8];

    int blk = blockIdx.x;
    int b = blk/80;
    int tid = threadIdx.x;

    if (tid < 8){
        float cnt = 64.f*(float)KK;
        float m = g_s3[b*8+tid]/cnt;
        float v = g_q3[b*8+tid]/cnt - m*m;
        sm3[tid] = m; sr3[tid] = rsqrtf(v + 1e-5f);
        s4[tid] = 0.f; q4[tid] = 0.f;
    }
    __syncthreads();

    for (int i=tid; i<512*KK; i+=256){
        int c = i/KK;
        int g = c>>6;
        float y = g_y3[(size_t)b*512*KK + i];
        float A = g3c[c]*sr3[g];
        sz[i] = elu1(fmaf(A, y, be3[c] - sm3[g]*A));
    }
    __syncthreads();

    int o = blk*256 + tid;
    int r = o - b*1024*KK;
    int c4 = r/KK, k = r%KK;
    float acc = b3[c4];
    const float* w = &w3[(size_t)c4*512];
#pragma unroll 8
    for (int j=0;j<512;j++) acc = fmaf(w[j], sz[j*KK+k], acc);
    g_y4[o] = acc;
    atomicAdd(&s4[c4>>7], acc);
    atomicAdd(&q4[c4>>7], acc*acc);
    __syncthreads();
    if (tid < 8){
        atomicAdd(&g_s4[b*8+tid], s4[tid]);
        atomicAdd(&g_q4[b*8+tid], q4[tid]);
    }
}

// ----------------------------- finalize -------------------------------------
__global__ void k_fin(const float* __restrict__ g4, const float* __restrict__ be4,
                      float* __restrict__ out){
    int o = blockIdx.x*256 + threadIdx.x;
    if (o >= BB*1024*KK) return;
    int b = o/(1024*KK);
    int r = o - b*1024*KK;
    int c = r/KK;
    int g = c>>7;
    float cnt = 128.f*(float)KK;
    float m = g_s4[b*8+g]/cnt;
    float v = g_q4[b*8+g]/cnt - m*m;
    float rs = rsqrtf(v + 1e-5f);
    float A = g4[c]*rs;
    out[o] = elu1(fmaf(A, g_y4[o], be4[c] - m*A));
}

// -----------------------------------------------------------------------------
extern "C" void kernel_launch(void* const* d_in, const int* in_sizes, int n_in,
                              void* d_out, int out_size){
    const float* pts  = (const float*)d_in[0];
    const float* p1w0 = (const float*)d_in[1];
    const float* p1b0 = (const float*)d_in[2];
    const float* p1g0 = (const float*)d_in[3];
    const float* p1be0= (const float*)d_in[4];
    const float* p1w1 = (const float*)d_in[5];
    const float* p1b1 = (const float*)d_in[6];
    const float* p1g1 = (const float*)d_in[7];
    const float* p1be1= (const float*)d_in[8];
    const float* p2w0 = (const float*)d_in[9];
    const float* p2b0 = (const float*)d_in[10];
    const float* p2g0 = (const float*)d_in[11];
    const float* p2be0= (const float*)d_in[12];
    const float* p2w1 = (const float*)d_in[13];
    const float* p2b1 = (const float*)d_in[14];
    const float* p2g1 = (const float*)d_in[15];
    const float* p2be1= (const float*)d_in[16];
    float* out = (float*)d_out;

    k_init<<<20, 256>>>();
    k_pack<<<(BB*NN+255)/256, 256>>>(pts);
    k_knn<<<dim3(NN/8, BB), 256>>>();
    k_gn1<<<1, 32>>>(p1w0, p1b0, p1g0, p1be0);
    k_pass2<<<dim3(NN/64, BB), 320>>>(p1w0, p1w1, p1b1);
    k_tail1<<<dim3(KK, BB), 512>>>(p1g1, p1be1, p2w0, p2b0);
    k_tail2<<<BB*80, 256>>>(p2g0, p2be0, p2w1, p2b1);
    k_fin<<<(BB*1024*KK + 255)/256, 256>>>(p2g1, p2be1, out);
}